// round 1
// baseline (speedup 1.0000x reference)
#include <cuda_runtime.h>
#include <math.h>

#define BB 4
#define NN 2048
#define DD 256
#define KK 16
#define PTS 4          // points per CTA in fused kernel
#define ROWS 64        // PTS * KK rows of x_k per CTA
#define KC 32          // K-chunk for weight streaming
#define SA 264         // padded smem row stride (floats)

__device__ int g_knn[BB * NN * KK];

// ---------------------------------------------------------------------------
// Kernel 1: exact KNN (k=16) per point. One warp per query point.
// ---------------------------------------------------------------------------
__global__ __launch_bounds__(256) void knn_kernel(const float* __restrict__ xyz) {
    __shared__ float sx[NN], sy[NN], sz[NN], ssq[NN];
    int b  = blockIdx.x >> 8;            // NN/8 = 256 CTAs per batch
    int q0 = (blockIdx.x & 255) * 8;     // 8 warps -> 8 queries per CTA
    const float* base = xyz + (size_t)b * NN * 3;
    for (int i = threadIdx.x; i < NN; i += 256) {
        float x = base[i * 3 + 0], y = base[i * 3 + 1], z = base[i * 3 + 2];
        sx[i] = x; sy[i] = y; sz[i] = z;
        ssq[i] = x * x + y * y + z * z;
    }
    __syncthreads();

    int lane = threadIdx.x & 31;
    int q = q0 + (threadIdx.x >> 5);
    float qx = sx[q], qy = sy[q], qz = sz[q], qsq = ssq[q];

    float bd[KK]; int bi[KK];
#pragma unroll
    for (int i = 0; i < KK; i++) { bd[i] = INFINITY; bi[i] = 0; }

    // per-lane sorted top-16 over strided candidates (registers only)
    for (int m = lane; m < NN; m += 32) {
        float d = qsq - 2.0f * (qx * sx[m] + qy * sy[m] + qz * sz[m]) + ssq[m];
        if (d < bd[KK - 1]) {
            float v = d; int vi = m;
#pragma unroll
            for (int j = 0; j < KK; j++) {
                if (v < bd[j]) {
                    float td = bd[j]; int ti = bi[j];
                    bd[j] = v; bi[j] = vi; v = td; vi = ti;
                }
            }
        }
    }

    // warp merge: 16 rounds of argmin over per-lane heads, winner shifts
    int sel = 0;
    for (int r = 0; r < KK; r++) {
        float m0 = bd[0]; int ml = lane;
#pragma unroll
        for (int off = 16; off; off >>= 1) {
            float om = __shfl_xor_sync(0xffffffffu, m0, off);
            int   ol = __shfl_xor_sync(0xffffffffu, ml, off);
            if (om < m0 || (om == m0 && ol < ml)) { m0 = om; ml = ol; }
        }
        int widx = __shfl_sync(0xffffffffu, bi[0], ml);
        if (lane == r) sel = widx;
        if (lane == ml) {
#pragma unroll
            for (int j = 0; j < KK - 1; j++) { bd[j] = bd[j + 1]; bi[j] = bi[j + 1]; }
            bd[KK - 1] = INFINITY;
        }
    }
    if (lane < KK) g_knn[((size_t)b * NN + q) * KK + lane] = sel;
}

// ---------------------------------------------------------------------------
// 64x256 = (64xK) @ (KxN) GEMM, A in smem (stride SA), W streamed from global
// through a 32x256 smem tile. Thread micro-tile: 4 rows x 16 cols.
// ---------------------------------------------------------------------------
__device__ __forceinline__ void gemm64(const float* __restrict__ Asrc,
                                       const float* __restrict__ W,
                                       float* __restrict__ Bs,
                                       float acc[4][16], int tid)
{
    int ty = tid >> 4, tx = tid & 15;
#pragma unroll
    for (int r = 0; r < 4; r++)
#pragma unroll
        for (int j = 0; j < 16; j++) acc[r][j] = 0.f;

    for (int kc = 0; kc < DD; kc += KC) {
        {   // stage weight chunk [kc..kc+31] x [0..255]
            const float4* Wv = (const float4*)(W + kc * DD);
            float4* Bv = (float4*)Bs;
#pragma unroll
            for (int i = 0; i < (KC * DD / 4) / 256; i++)
                Bv[tid + i * 256] = Wv[tid + i * 256];
        }
        __syncthreads();
#pragma unroll 4
        for (int kk = 0; kk < KC; kk++) {
            float a[4];
#pragma unroll
            for (int r = 0; r < 4; r++) a[r] = Asrc[(ty * 4 + r) * SA + kc + kk];
#pragma unroll
            for (int j4 = 0; j4 < 4; j4++) {
                float4 bv = *(const float4*)&Bs[kk * DD + tx * 16 + j4 * 4];
#pragma unroll
                for (int r = 0; r < 4; r++) {
                    acc[r][j4 * 4 + 0] = fmaf(a[r], bv.x, acc[r][j4 * 4 + 0]);
                    acc[r][j4 * 4 + 1] = fmaf(a[r], bv.y, acc[r][j4 * 4 + 1]);
                    acc[r][j4 * 4 + 2] = fmaf(a[r], bv.z, acc[r][j4 * 4 + 2]);
                    acc[r][j4 * 4 + 3] = fmaf(a[r], bv.w, acc[r][j4 * 4 + 3]);
                }
            }
        }
        __syncthreads();
    }
}

// ---------------------------------------------------------------------------
// Kernel 2: fused delta-MLP + gather + gating-MLP + softmax + residual.
// One CTA = 4 points (64 x_k rows). All intermediates live in smem.
// ---------------------------------------------------------------------------
__global__ __launch_bounds__(256, 1)
void mlp_kernel(const float* __restrict__ xyz, const float* __restrict__ feat,
                const float* __restrict__ wd1, const float* __restrict__ bd1,
                const float* __restrict__ wd2, const float* __restrict__ bd2,
                const float* __restrict__ wg1, const float* __restrict__ bg1,
                const float* __restrict__ wg2, const float* __restrict__ bg2,
                float* __restrict__ out)
{
    extern __shared__ float smf[];
    float* As   = smf;                    // 64 x SA  (H1 -> H2 -> G)
    float* Xs   = As + ROWS * SA;         // 64 x SA  (x_k)
    float* Bs   = Xs + ROWS * SA;         // 32 x 256 weight tile
    float* sdel = Bs + KC * DD;           // 64 x 3
    int*   sidx = (int*)(sdel + ROWS * 3);// 64

    int tid = threadIdx.x;
    int b   = blockIdx.x >> 9;            // NN/PTS = 512
    int p0  = (blockIdx.x & 511) * PTS;

    if (tid < ROWS) {
        int p = tid >> 4, kn = tid & 15;
        int n = p0 + p;
        int idx = g_knn[((size_t)b * NN + n) * KK + kn];
        sidx[tid] = idx;
        const float* xb = xyz + (size_t)b * NN * 3;
        sdel[tid * 3 + 0] = xb[n * 3 + 0] - xb[idx * 3 + 0];
        sdel[tid * 3 + 1] = xb[n * 3 + 1] - xb[idx * 3 + 1];
        sdel[tid * 3 + 2] = xb[n * 3 + 2] - xb[idx * 3 + 2];
    }
    __syncthreads();

    // H1 = relu(delta @ wd1 + bd1)  -> As  (each thread owns one channel)
    {
        float w0 = wd1[tid], w1 = wd1[DD + tid], w2 = wd1[2 * DD + tid], b0 = bd1[tid];
        for (int r = 0; r < ROWS; r++) {
            float h = fmaf(sdel[r * 3 + 2], w2,
                      fmaf(sdel[r * 3 + 1], w1,
                      fmaf(sdel[r * 3 + 0], w0, b0)));
            As[r * SA + tid] = fmaxf(h, 0.f);
        }
    }
    __syncthreads();

    int ty = tid >> 4, tx = tid & 15;
    float acc[4][16];

    // GEMM1: x_k = H1 @ wd2 + bd2 + feat[knn_idx]  -> Xs
    gemm64(As, wd2, Bs, acc, tid);
    {
        const float* fb = feat + (size_t)b * NN * DD;
        float bias[16];
#pragma unroll
        for (int j = 0; j < 16; j++) bias[j] = bd2[tx * 16 + j];
#pragma unroll
        for (int r = 0; r < 4; r++) {
            int row = ty * 4 + r;
            const float* fr = fb + (size_t)sidx[row] * DD + tx * 16;
#pragma unroll
            for (int j4 = 0; j4 < 4; j4++) {
                float4 f = *(const float4*)(fr + j4 * 4);
                Xs[row * SA + tx * 16 + j4 * 4 + 0] = acc[r][j4 * 4 + 0] + bias[j4 * 4 + 0] + f.x;
                Xs[row * SA + tx * 16 + j4 * 4 + 1] = acc[r][j4 * 4 + 1] + bias[j4 * 4 + 1] + f.y;
                Xs[row * SA + tx * 16 + j4 * 4 + 2] = acc[r][j4 * 4 + 2] + bias[j4 * 4 + 2] + f.z;
                Xs[row * SA + tx * 16 + j4 * 4 + 3] = acc[r][j4 * 4 + 3] + bias[j4 * 4 + 3] + f.w;
            }
        }
    }

    // GEMM2: H2 = relu(x_k @ wg1 + bg1)  -> As
    gemm64(Xs, wg1, Bs, acc, tid);
    {
        float bias[16];
#pragma unroll
        for (int j = 0; j < 16; j++) bias[j] = bg1[tx * 16 + j];
#pragma unroll
        for (int r = 0; r < 4; r++)
#pragma unroll
            for (int j = 0; j < 16; j++)
                As[(ty * 4 + r) * SA + tx * 16 + j] = fmaxf(acc[r][j] + bias[j], 0.f);
    }

    // GEMM3: G = H2 @ wg2 + bg2  (accumulate in regs, then overwrite As)
    gemm64(As, wg2, Bs, acc, tid);
    {
        float bias[16];
#pragma unroll
        for (int j = 0; j < 16; j++) bias[j] = bg2[tx * 16 + j];
#pragma unroll
        for (int r = 0; r < 4; r++)
#pragma unroll
            for (int j = 0; j < 16; j++)
                As[(ty * 4 + r) * SA + tx * 16 + j] = acc[r][j] + bias[j];
    }
    __syncthreads();

    // softmax over k per channel + weighted sum + residual
    {
        int p  = tid >> 6;       // 0..3
        int d0 = tid & 63;
        int n  = p0 + p;
        const float* fr = feat + ((size_t)b * NN + n) * DD;
        float* orow = out + ((size_t)b * NN + n) * DD;
#pragma unroll
        for (int i = 0; i < 4; i++) {
            int d = d0 + i * 64;
            float mx = -INFINITY;
#pragma unroll
            for (int k = 0; k < KK; k++) mx = fmaxf(mx, As[(p * KK + k) * SA + d]);
            float e[KK]; float s = 0.f;
#pragma unroll
            for (int k = 0; k < KK; k++) {
                e[k] = expf(As[(p * KK + k) * SA + d] - mx);
                s += e[k];
            }
            float inv = 1.f / s;
            float res = 0.f;
#pragma unroll
            for (int k = 0; k < KK; k++) res += e[k] * Xs[(p * KK + k) * SA + d];
            orow[d] = fr[d] + res * inv;
        }
    }
}

// ---------------------------------------------------------------------------
extern "C" void kernel_launch(void* const* d_in, const int* in_sizes, int n_in,
                              void* d_out, int out_size) {
    const float* xyz  = (const float*)d_in[0];
    const float* feat = (const float*)d_in[1];
    const float* wd1  = (const float*)d_in[2];
    const float* bd1  = (const float*)d_in[3];
    const float* wd2  = (const float*)d_in[4];
    const float* bd2  = (const float*)d_in[5];
    const float* wg1  = (const float*)d_in[6];
    const float* bg1  = (const float*)d_in[7];
    const float* wg2  = (const float*)d_in[8];
    const float* bg2  = (const float*)d_in[9];
    float* out = (float*)d_out;

    knn_kernel<<<BB * NN / 8, 256>>>(xyz);

    int smem = (ROWS * SA * 2 + KC * DD + ROWS * 3) * 4 + ROWS * 4;  // ~169 KB
    cudaFuncSetAttribute(mlp_kernel, cudaFuncAttributeMaxDynamicSharedMemorySize, smem);
    mlp_kernel<<<BB * NN / PTS, 256, smem>>>(xyz, feat, wd1, bd1, wd2, bd2,
                                             wg1, bg1, wg2, bg2, out);
}

// round 3
// speedup vs baseline: 1.5865x; 1.5865x over previous
#include <cuda_runtime.h>
#include <stdint.h>
#include <math.h>

#define BB 4
#define NN 2048
#define DD 256
#define KK 16
#define PTS 4          // points per CTA in fused kernel
#define ROWS 64        // PTS * KK rows of x_k per CTA
#define KC 32          // K-chunk for weight streaming
#define SA 264         // padded smem row stride (floats)
#define NT 512         // threads per CTA (fused kernel)

__device__ int g_knn[BB * NN * KK];

// ---------------------------------------------------------------------------
// Kernel 1: exact KNN (k=16) per point. One warp per query point.
// ---------------------------------------------------------------------------
__global__ __launch_bounds__(256) void knn_kernel(const float* __restrict__ xyz) {
    __shared__ float sx[NN], sy[NN], sz[NN], ssq[NN];
    int b  = blockIdx.x >> 8;
    int q0 = (blockIdx.x & 255) * 8;
    const float* base = xyz + (size_t)b * NN * 3;
    for (int i = threadIdx.x; i < NN; i += 256) {
        float x = base[i * 3 + 0], y = base[i * 3 + 1], z = base[i * 3 + 2];
        sx[i] = x; sy[i] = y; sz[i] = z;
        ssq[i] = x * x + y * y + z * z;
    }
    __syncthreads();

    int lane = threadIdx.x & 31;
    int q = q0 + (threadIdx.x >> 5);
    float qx = sx[q], qy = sy[q], qz = sz[q], qsq = ssq[q];

    float bd[KK]; int bi[KK];
#pragma unroll
    for (int i = 0; i < KK; i++) { bd[i] = INFINITY; bi[i] = 0; }

    for (int m = lane; m < NN; m += 32) {
        float d = qsq - 2.0f * (qx * sx[m] + qy * sy[m] + qz * sz[m]) + ssq[m];
        if (d < bd[KK - 1]) {
            float v = d; int vi = m;
#pragma unroll
            for (int j = 0; j < KK; j++) {
                if (v < bd[j]) {
                    float td = bd[j]; int ti = bi[j];
                    bd[j] = v; bi[j] = vi; v = td; vi = ti;
                }
            }
        }
    }

    int sel = 0;
    for (int r = 0; r < KK; r++) {
        float m0 = bd[0]; int ml = lane;
#pragma unroll
        for (int off = 16; off; off >>= 1) {
            float om = __shfl_xor_sync(0xffffffffu, m0, off);
            int   ol = __shfl_xor_sync(0xffffffffu, ml, off);
            if (om < m0 || (om == m0 && ol < ml)) { m0 = om; ml = ol; }
        }
        int widx = __shfl_sync(0xffffffffu, bi[0], ml);
        if (lane == r) sel = widx;
        if (lane == ml) {
#pragma unroll
            for (int j = 0; j < KK - 1; j++) { bd[j] = bd[j + 1]; bi[j] = bi[j + 1]; }
            bd[KK - 1] = INFINITY;
        }
    }
    if (lane < KK) g_knn[((size_t)b * NN + q) * KK + lane] = sel;
}

// ---------------------------------------------------------------------------
// cp.async helpers
// ---------------------------------------------------------------------------
__device__ __forceinline__ void cp_async16(float* smem, const float* gmem) {
    unsigned int a = (unsigned int)__cvta_generic_to_shared(smem);
    asm volatile("cp.async.cg.shared.global [%0], [%1], 16;\n" :: "r"(a), "l"(gmem));
}
__device__ __forceinline__ void cp_commit() { asm volatile("cp.async.commit_group;\n"); }
__device__ __forceinline__ void cp_wait0()  { asm volatile("cp.async.wait_group 0;\n" ::: "memory"); }

// Stage one KC x 256 weight chunk into Bs with a permuted cell layout:
// logical col c = tx*16 + j4*4 + e  stored at float offset  k*DD + j4*64 + tx*4 + e
// so compute-side LDS.128 across tx lanes hits 256 contiguous bytes (conflict-free).
__device__ __forceinline__ void stage(const float* __restrict__ W, float* __restrict__ Bs,
                                      int chunk, int tid) {
    const float* src = W + chunk * KC * DD;
#pragma unroll
    for (int i = 0; i < (KC * DD / 4) / NT; i++) {
        int id = tid + i * NT;            // float4 cell id, 0..2047
        int k  = id >> 6;                 // row within chunk
        int s  = id & 63;                 // source float4 within row
        int tx = s >> 2, j4 = s & 3;
        cp_async16(Bs + k * DD + j4 * 64 + tx * 4, src + k * DD + s * 4);
    }
    cp_commit();
}

// ---------------------------------------------------------------------------
// 64x256 = (64x256) @ (256x256), A in smem (stride SA), W double-buffered.
// Thread micro-tile: 2 rows x 16 cols. 512 threads.
// ---------------------------------------------------------------------------
__device__ __forceinline__ void gemm64(const float* __restrict__ Asrc,
                                       const float* __restrict__ W,
                                       float* __restrict__ Bs0,
                                       float* __restrict__ Bs1,
                                       float acc[2][16], int tid)
{
    int ty = tid >> 4, tx = tid & 15;
#pragma unroll
    for (int r = 0; r < 2; r++)
#pragma unroll
        for (int j = 0; j < 16; j++) acc[r][j] = 0.f;

    __syncthreads();                 // prior epilogue writes visible; prior Bs reads done
    stage(W, Bs0, 0, tid);

#pragma unroll 1
    for (int c = 0; c < DD / KC; c++) {
        cp_wait0();
        __syncthreads();
        const float* Bs = (c & 1) ? Bs1 : Bs0;
        if (c + 1 < DD / KC) stage(W, (c & 1) ? Bs0 : Bs1, c + 1, tid);
        int kc = c * KC;
        const float* a0p = Asrc + (ty * 2 + 0) * SA + kc;
        const float* a1p = Asrc + (ty * 2 + 1) * SA + kc;
#pragma unroll
        for (int k4 = 0; k4 < KC / 4; k4++) {
            float4 a0 = *(const float4*)(a0p + k4 * 4);
            float4 a1 = *(const float4*)(a1p + k4 * 4);
            float av0[4] = {a0.x, a0.y, a0.z, a0.w};
            float av1[4] = {a1.x, a1.y, a1.z, a1.w};
#pragma unroll
            for (int kk = 0; kk < 4; kk++) {
                const float* brow = Bs + (k4 * 4 + kk) * DD + tx * 4;
#pragma unroll
                for (int j4 = 0; j4 < 4; j4++) {
                    float4 bv = *(const float4*)(brow + j4 * 64);
                    acc[0][j4 * 4 + 0] = fmaf(av0[kk], bv.x, acc[0][j4 * 4 + 0]);
                    acc[0][j4 * 4 + 1] = fmaf(av0[kk], bv.y, acc[0][j4 * 4 + 1]);
                    acc[0][j4 * 4 + 2] = fmaf(av0[kk], bv.z, acc[0][j4 * 4 + 2]);
                    acc[0][j4 * 4 + 3] = fmaf(av0[kk], bv.w, acc[0][j4 * 4 + 3]);
                    acc[1][j4 * 4 + 0] = fmaf(av1[kk], bv.x, acc[1][j4 * 4 + 0]);
                    acc[1][j4 * 4 + 1] = fmaf(av1[kk], bv.y, acc[1][j4 * 4 + 1]);
                    acc[1][j4 * 4 + 2] = fmaf(av1[kk], bv.z, acc[1][j4 * 4 + 2]);
                    acc[1][j4 * 4 + 3] = fmaf(av1[kk], bv.w, acc[1][j4 * 4 + 3]);
                }
            }
        }
    }
    __syncthreads();                 // all reads of Asrc done before caller overwrites
}

// ---------------------------------------------------------------------------
// Kernel 2: fused delta-MLP + gather + gating-MLP + softmax + residual.
// One CTA = 4 points (64 x_k rows). All intermediates live in smem.
// ---------------------------------------------------------------------------
__global__ __launch_bounds__(NT, 1)
void mlp_kernel(const float* __restrict__ xyz, const float* __restrict__ feat,
                const float* __restrict__ wd1, const float* __restrict__ bd1,
                const float* __restrict__ wd2, const float* __restrict__ bd2,
                const float* __restrict__ wg1, const float* __restrict__ bg1,
                const float* __restrict__ wg2, const float* __restrict__ bg2,
                float* __restrict__ out)
{
    extern __shared__ float smf[];
    float* As   = smf;                     // 64 x SA  (H1 -> H2 -> G)
    float* Xs   = As + ROWS * SA;          // 64 x SA  (x_k)
    float* Bs0  = Xs + ROWS * SA;          // 32 x 256 weight tile (buf 0)
    float* Bs1  = Bs0 + KC * DD;           // 32 x 256 weight tile (buf 1)
    float* sdel = Bs1 + KC * DD;           // 64 x 3
    int*   sidx = (int*)(sdel + ROWS * 3); // 64

    int tid = threadIdx.x;
    int b   = blockIdx.x >> 9;             // NN/PTS = 512 CTAs per batch
    int p0  = (blockIdx.x & 511) * PTS;

    if (tid < ROWS) {
        int p = tid >> 4, kn = tid & 15;
        int n = p0 + p;
        int idx = g_knn[((size_t)b * NN + n) * KK + kn];
        sidx[tid] = idx;
        const float* xb = xyz + (size_t)b * NN * 3;
        sdel[tid * 3 + 0] = xb[n * 3 + 0] - xb[idx * 3 + 0];
        sdel[tid * 3 + 1] = xb[n * 3 + 1] - xb[idx * 3 + 1];
        sdel[tid * 3 + 2] = xb[n * 3 + 2] - xb[idx * 3 + 2];
    }
    __syncthreads();

    // H1 = relu(delta @ wd1 + bd1) -> As. 512 threads: thread owns (channel, half).
    {
        int ch = tid & 255;
        int r0 = (tid >> 8) * (ROWS / 2);
        float w0 = wd1[ch], w1 = wd1[DD + ch], w2 = wd1[2 * DD + ch], b0 = bd1[ch];
        for (int r = r0; r < r0 + ROWS / 2; r++) {
            float h = fmaf(sdel[r * 3 + 2], w2,
                      fmaf(sdel[r * 3 + 1], w1,
                      fmaf(sdel[r * 3 + 0], w0, b0)));
            As[r * SA + ch] = fmaxf(h, 0.f);
        }
    }
    // gemm64 starts with __syncthreads()

    int ty = tid >> 4, tx = tid & 15;
    float acc[2][16];

    // GEMM1: x_k = H1 @ wd2 + bd2 + feat[knn_idx] -> Xs
    gemm64(As, wd2, Bs0, Bs1, acc, tid);
    {
        const float* fb = feat + (size_t)b * NN * DD;
        float bias[16];
#pragma unroll
        for (int j = 0; j < 16; j++) bias[j] = bd2[tx * 16 + j];
#pragma unroll
        for (int r = 0; r < 2; r++) {
            int row = ty * 2 + r;
            const float* fr = fb + (size_t)sidx[row] * DD + tx * 16;
#pragma unroll
            for (int j4 = 0; j4 < 4; j4++) {
                float4 f = *(const float4*)(fr + j4 * 4);
                Xs[row * SA + tx * 16 + j4 * 4 + 0] = acc[r][j4 * 4 + 0] + bias[j4 * 4 + 0] + f.x;
                Xs[row * SA + tx * 16 + j4 * 4 + 1] = acc[r][j4 * 4 + 1] + bias[j4 * 4 + 1] + f.y;
                Xs[row * SA + tx * 16 + j4 * 4 + 2] = acc[r][j4 * 4 + 2] + bias[j4 * 4 + 2] + f.z;
                Xs[row * SA + tx * 16 + j4 * 4 + 3] = acc[r][j4 * 4 + 3] + bias[j4 * 4 + 3] + f.w;
            }
        }
    }

    // GEMM2: H2 = relu(x_k @ wg1 + bg1) -> As
    gemm64(Xs, wg1, Bs0, Bs1, acc, tid);
    {
        float bias[16];
#pragma unroll
        for (int j = 0; j < 16; j++) bias[j] = bg1[tx * 16 + j];
#pragma unroll
        for (int r = 0; r < 2; r++)
#pragma unroll
            for (int j = 0; j < 16; j++)
                As[(ty * 2 + r) * SA + tx * 16 + j] = fmaxf(acc[r][j] + bias[j], 0.f);
    }

    // GEMM3: G = H2 @ wg2 + bg2 -> As (trailing barrier in gemm64 makes this safe)
    gemm64(As, wg2, Bs0, Bs1, acc, tid);
    {
        float bias[16];
#pragma unroll
        for (int j = 0; j < 16; j++) bias[j] = bg2[tx * 16 + j];
#pragma unroll
        for (int r = 0; r < 2; r++)
#pragma unroll
            for (int j = 0; j < 16; j++)
                As[(ty * 2 + r) * SA + tx * 16 + j] = acc[r][j] + bias[j];
    }
    __syncthreads();

    // softmax over k per channel + weighted sum + residual. 512 threads:
    // thread handles (point p, channels d0 and d0+128).
    {
        int p  = tid >> 7;        // 0..3
        int d0 = tid & 127;
        int n  = p0 + p;
        const float* fr = feat + ((size_t)b * NN + n) * DD;
        float* orow = out + ((size_t)b * NN + n) * DD;
#pragma unroll
        for (int i = 0; i < 2; i++) {
            int d = d0 + i * 128;
            float mx = -INFINITY;
#pragma unroll
            for (int k = 0; k < KK; k++) mx = fmaxf(mx, As[(p * KK + k) * SA + d]);
            float e[KK]; float s = 0.f;
#pragma unroll
            for (int k = 0; k < KK; k++) {
                e[k] = expf(As[(p * KK + k) * SA + d] - mx);
                s += e[k];
            }
            float inv = 1.f / s;
            float res = 0.f;
#pragma unroll
            for (int k = 0; k < KK; k++) res += e[k] * Xs[(p * KK + k) * SA + d];
            orow[d] = fr[d] + res * inv;
        }
    }
}

// ---------------------------------------------------------------------------
extern "C" void kernel_launch(void* const* d_in, const int* in_sizes, int n_in,
                              void* d_out, int out_size) {
    const float* xyz  = (const float*)d_in[0];
    const float* feat = (const float*)d_in[1];
    const float* wd1  = (const float*)d_in[2];
    const float* bd1  = (const float*)d_in[3];
    const float* wd2  = (const float*)d_in[4];
    const float* bd2  = (const float*)d_in[5];
    const float* wg1  = (const float*)d_in[6];
    const float* bg1  = (const float*)d_in[7];
    const float* wg2  = (const float*)d_in[8];
    const float* bg2  = (const float*)d_in[9];
    float* out = (float*)d_out;

    knn_kernel<<<BB * NN / 8, 256>>>(xyz);

    int smem = (ROWS * SA * 2 + 2 * KC * DD + ROWS * 3) * 4 + ROWS * 4;  // ~202 KB
    cudaFuncSetAttribute(mlp_kernel, cudaFuncAttributeMaxDynamicSharedMemorySize, smem);
    mlp_kernel<<<BB * NN / PTS, NT, smem>>>(xyz, feat, wd1, bd1, wd2, bd2,
                                            wg1, bg1, wg2, bg2, out);
}

// round 4
// speedup vs baseline: 2.0199x; 1.2732x over previous
#include <cuda_runtime.h>
#include <stdint.h>
#include <math.h>

#define BB 4
#define NN 2048
#define DD 256
#define KK 16
#define PTS 4          // points per CTA in fused kernel
#define ROWS 64        // PTS * KK rows of x_k per CTA
#define KC 32          // K-chunk for weight streaming
#define SA 264         // padded smem row stride (floats)
#define NT 512         // threads per CTA (fused kernel)

__device__ int g_knn[BB * NN * KK];

// ---------------------------------------------------------------------------
// Kernel 1: exact KNN (k=16) per point. One warp per query point.
// ---------------------------------------------------------------------------
__global__ __launch_bounds__(256) void knn_kernel(const float* __restrict__ xyz) {
    __shared__ float sx[NN], sy[NN], sz[NN], ssq[NN];
    int b  = blockIdx.x >> 8;
    int q0 = (blockIdx.x & 255) * 8;
    const float* base = xyz + (size_t)b * NN * 3;
    for (int i = threadIdx.x; i < NN; i += 256) {
        float x = base[i * 3 + 0], y = base[i * 3 + 1], z = base[i * 3 + 2];
        sx[i] = x; sy[i] = y; sz[i] = z;
        ssq[i] = x * x + y * y + z * z;
    }
    __syncthreads();

    int lane = threadIdx.x & 31;
    int q = q0 + (threadIdx.x >> 5);
    float qx = sx[q], qy = sy[q], qz = sz[q], qsq = ssq[q];

    float bd[KK]; int bi[KK];
#pragma unroll
    for (int i = 0; i < KK; i++) { bd[i] = INFINITY; bi[i] = 0; }

    for (int m = lane; m < NN; m += 32) {
        float d = qsq - 2.0f * (qx * sx[m] + qy * sy[m] + qz * sz[m]) + ssq[m];
        if (d < bd[KK - 1]) {
            float v = d; int vi = m;
#pragma unroll
            for (int j = 0; j < KK; j++) {
                if (v < bd[j]) {
                    float td = bd[j]; int ti = bi[j];
                    bd[j] = v; bi[j] = vi; v = td; vi = ti;
                }
            }
        }
    }

    int sel = 0;
    for (int r = 0; r < KK; r++) {
        float m0 = bd[0]; int ml = lane;
#pragma unroll
        for (int off = 16; off; off >>= 1) {
            float om = __shfl_xor_sync(0xffffffffu, m0, off);
            int   ol = __shfl_xor_sync(0xffffffffu, ml, off);
            if (om < m0 || (om == m0 && ol < ml)) { m0 = om; ml = ol; }
        }
        int widx = __shfl_sync(0xffffffffu, bi[0], ml);
        if (lane == r) sel = widx;
        if (lane == ml) {
#pragma unroll
            for (int j = 0; j < KK - 1; j++) { bd[j] = bd[j + 1]; bi[j] = bi[j + 1]; }
            bd[KK - 1] = INFINITY;
        }
    }
    if (lane < KK) g_knn[((size_t)b * NN + q) * KK + lane] = sel;
}

// ---------------------------------------------------------------------------
// cp.async helpers
// ---------------------------------------------------------------------------
__device__ __forceinline__ void cp_async16(float* smem, const float* gmem) {
    unsigned int a = (unsigned int)__cvta_generic_to_shared(smem);
    asm volatile("cp.async.cg.shared.global [%0], [%1], 16;\n" :: "r"(a), "l"(gmem));
}
__device__ __forceinline__ void cp_commit() { asm volatile("cp.async.commit_group;\n"); }
__device__ __forceinline__ void cp_wait0()  { asm volatile("cp.async.wait_group 0;\n" ::: "memory"); }

// Stage one KC x 256 weight chunk into Bs, lane-interleaved:
// source float4 cell s (cols 4s..4s+3) of row k goes to cell ((s&1)*32 + (s>>1)).
// Compute-side: lane l reads cells l (cols l*8..l*8+3) and 32+l (cols l*8+4..l*8+7);
// both LDS.128 span 512 contiguous bytes across the warp -> conflict-free.
__device__ __forceinline__ void stage(const float* __restrict__ W, float* __restrict__ Bs,
                                      int chunk, int tid) {
    const float* src = W + chunk * KC * DD;
#pragma unroll
    for (int i = 0; i < (KC * DD / 4) / NT; i++) {
        int id = tid + i * NT;            // float4 cell id, 0..2047
        int k  = id >> 6;                 // row within chunk
        int s  = id & 63;                 // source float4 within row
        int dc = (s & 1) * 32 + (s >> 1); // interleaved destination cell
        cp_async16(Bs + k * DD + dc * 4, src + k * DD + s * 4);
    }
    cp_commit();
}

// ---------------------------------------------------------------------------
// 64x256 = (64x256) @ (256x256), A in smem (stride SA), W double-buffered.
// Thread micro-tile: 4 rows x 8 cols. warp = 4 rows, lane = cols [l*8, l*8+8).
// ---------------------------------------------------------------------------
__device__ __forceinline__ void gemm64(const float* __restrict__ Asrc,
                                       const float* __restrict__ W,
                                       float* __restrict__ Bs0,
                                       float* __restrict__ Bs1,
                                       float acc[4][8], int tid)
{
    int w = tid >> 5, l = tid & 31;
#pragma unroll
    for (int r = 0; r < 4; r++)
#pragma unroll
        for (int j = 0; j < 8; j++) acc[r][j] = 0.f;

    __syncthreads();                 // prior epilogue writes visible; prior Bs reads done
    stage(W, Bs0, 0, tid);

#pragma unroll 1
    for (int c = 0; c < DD / KC; c++) {
        cp_wait0();
        __syncthreads();
        const float* Bs = (c & 1) ? Bs1 : Bs0;
        if (c + 1 < DD / KC) stage(W, (c & 1) ? Bs0 : Bs1, c + 1, tid);
        int kc = c * KC;
        const float* ap = Asrc + (w * 4) * SA + kc;
#pragma unroll
        for (int k4 = 0; k4 < KC / 4; k4++) {
            float4 a0 = *(const float4*)(ap + 0 * SA + k4 * 4);
            float4 a1 = *(const float4*)(ap + 1 * SA + k4 * 4);
            float4 a2 = *(const float4*)(ap + 2 * SA + k4 * 4);
            float4 a3 = *(const float4*)(ap + 3 * SA + k4 * 4);
            float av[4][4] = {{a0.x, a0.y, a0.z, a0.w}, {a1.x, a1.y, a1.z, a1.w},
                              {a2.x, a2.y, a2.z, a2.w}, {a3.x, a3.y, a3.z, a3.w}};
#pragma unroll
            for (int kk = 0; kk < 4; kk++) {
                const float* brow = Bs + (k4 * 4 + kk) * DD;
                float4 b0 = *(const float4*)(brow + l * 4);        // cols l*8..+3
                float4 b1 = *(const float4*)(brow + 128 + l * 4);  // cols l*8+4..+7
#pragma unroll
                for (int r = 0; r < 4; r++) {
                    acc[r][0] = fmaf(av[r][kk], b0.x, acc[r][0]);
                    acc[r][1] = fmaf(av[r][kk], b0.y, acc[r][1]);
                    acc[r][2] = fmaf(av[r][kk], b0.z, acc[r][2]);
                    acc[r][3] = fmaf(av[r][kk], b0.w, acc[r][3]);
                    acc[r][4] = fmaf(av[r][kk], b1.x, acc[r][4]);
                    acc[r][5] = fmaf(av[r][kk], b1.y, acc[r][5]);
                    acc[r][6] = fmaf(av[r][kk], b1.z, acc[r][6]);
                    acc[r][7] = fmaf(av[r][kk], b1.w, acc[r][7]);
                }
            }
        }
    }
    __syncthreads();                 // all reads of Asrc done before caller overwrites
}

// ---------------------------------------------------------------------------
// Kernel 2: fused delta-MLP + gather + gating-MLP + softmax + residual.
// One CTA = 4 points (64 x_k rows). All intermediates live in smem.
// ---------------------------------------------------------------------------
__global__ __launch_bounds__(NT, 1)
void mlp_kernel(const float* __restrict__ xyz, const float* __restrict__ feat,
                const float* __restrict__ wd1, const float* __restrict__ bd1,
                const float* __restrict__ wd2, const float* __restrict__ bd2,
                const float* __restrict__ wg1, const float* __restrict__ bg1,
                const float* __restrict__ wg2, const float* __restrict__ bg2,
                float* __restrict__ out)
{
    extern __shared__ float smf[];
    float* As   = smf;                     // 64 x SA  (H1 -> H2 -> G)
    float* Xs   = As + ROWS * SA;          // 64 x SA  (x_k)
    float* Bs0  = Xs + ROWS * SA;          // 32 x 256 weight tile (buf 0)
    float* Bs1  = Bs0 + KC * DD;           // 32 x 256 weight tile (buf 1)
    float* sdel = Bs1 + KC * DD;           // 64 x 3
    int*   sidx = (int*)(sdel + ROWS * 3); // 64

    int tid = threadIdx.x;
    int b   = blockIdx.x >> 9;             // NN/PTS = 512 CTAs per batch
    int p0  = (blockIdx.x & 511) * PTS;

    if (tid < ROWS) {
        int p = tid >> 4, kn = tid & 15;
        int n = p0 + p;
        int idx = g_knn[((size_t)b * NN + n) * KK + kn];
        sidx[tid] = idx;
        const float* xb = xyz + (size_t)b * NN * 3;
        sdel[tid * 3 + 0] = xb[n * 3 + 0] - xb[idx * 3 + 0];
        sdel[tid * 3 + 1] = xb[n * 3 + 1] - xb[idx * 3 + 1];
        sdel[tid * 3 + 2] = xb[n * 3 + 2] - xb[idx * 3 + 2];
    }
    __syncthreads();

    // H1 = relu(delta @ wd1 + bd1) -> As. 512 threads: thread owns (channel, half).
    {
        int ch = tid & 255;
        int r0 = (tid >> 8) * (ROWS / 2);
        float w0 = wd1[ch], w1 = wd1[DD + ch], w2 = wd1[2 * DD + ch], b0 = bd1[ch];
        for (int r = r0; r < r0 + ROWS / 2; r++) {
            float h = fmaf(sdel[r * 3 + 2], w2,
                      fmaf(sdel[r * 3 + 1], w1,
                      fmaf(sdel[r * 3 + 0], w0, b0)));
            As[r * SA + ch] = fmaxf(h, 0.f);
        }
    }
    // gemm64 starts with __syncthreads()

    int w = tid >> 5, l = tid & 31;
    float acc[4][8];

    // GEMM1: x_k = H1 @ wd2 + bd2 + feat[knn_idx] -> Xs
    gemm64(As, wd2, Bs0, Bs1, acc, tid);
    {
        const float* fb = feat + (size_t)b * NN * DD;
        float bias[8];
#pragma unroll
        for (int j = 0; j < 8; j++) bias[j] = bd2[l * 8 + j];
#pragma unroll
        for (int r = 0; r < 4; r++) {
            int row = w * 4 + r;
            const float* fr = fb + (size_t)sidx[row] * DD + l * 8;
            float4 f0 = *(const float4*)(fr + 0);
            float4 f1 = *(const float4*)(fr + 4);
            float* xr = Xs + row * SA + l * 8;
            xr[0] = acc[r][0] + bias[0] + f0.x;
            xr[1] = acc[r][1] + bias[1] + f0.y;
            xr[2] = acc[r][2] + bias[2] + f0.z;
            xr[3] = acc[r][3] + bias[3] + f0.w;
            xr[4] = acc[r][4] + bias[4] + f1.x;
            xr[5] = acc[r][5] + bias[5] + f1.y;
            xr[6] = acc[r][6] + bias[6] + f1.z;
            xr[7] = acc[r][7] + bias[7] + f1.w;
        }
    }

    // GEMM2: H2 = relu(x_k @ wg1 + bg1) -> As
    gemm64(Xs, wg1, Bs0, Bs1, acc, tid);
    {
        float bias[8];
#pragma unroll
        for (int j = 0; j < 8; j++) bias[j] = bg1[l * 8 + j];
#pragma unroll
        for (int r = 0; r < 4; r++)
#pragma unroll
            for (int j = 0; j < 8; j++)
                As[(w * 4 + r) * SA + l * 8 + j] = fmaxf(acc[r][j] + bias[j], 0.f);
    }

    // GEMM3: G = H2 @ wg2 + bg2 -> As (trailing barrier in gemm64 makes this safe)
    gemm64(As, wg2, Bs0, Bs1, acc, tid);
    {
        float bias[8];
#pragma unroll
        for (int j = 0; j < 8; j++) bias[j] = bg2[l * 8 + j];
#pragma unroll
        for (int r = 0; r < 4; r++)
#pragma unroll
            for (int j = 0; j < 8; j++)
                As[(w * 4 + r) * SA + l * 8 + j] = acc[r][j] + bias[j];
    }
    __syncthreads();

    // softmax over k per channel + weighted sum + residual. 512 threads:
    // thread handles (point p, channels d0 and d0+128).
    {
        int p  = tid >> 7;        // 0..3
        int d0 = tid & 127;
        int n  = p0 + p;
        const float* fr = feat + ((size_t)b * NN + n) * DD;
        float* orow = out + ((size_t)b * NN + n) * DD;
#pragma unroll
        for (int i = 0; i < 2; i++) {
            int d = d0 + i * 128;
            float mx = -INFINITY;
#pragma unroll
            for (int k = 0; k < KK; k++) mx = fmaxf(mx, As[(p * KK + k) * SA + d]);
            float e[KK]; float s = 0.f;
#pragma unroll
            for (int k = 0; k < KK; k++) {
                e[k] = expf(As[(p * KK + k) * SA + d] - mx);
                s += e[k];
            }
            float inv = 1.f / s;
            float res = 0.f;
#pragma unroll
            for (int k = 0; k < KK; k++) res += e[k] * Xs[(p * KK + k) * SA + d];
            orow[d] = fr[d] + res * inv;
        }
    }
}

// ---------------------------------------------------------------------------
extern "C" void kernel_launch(void* const* d_in, const int* in_sizes, int n_in,
                              void* d_out, int out_size) {
    const float* xyz  = (const float*)d_in[0];
    const float* feat = (const float*)d_in[1];
    const float* wd1  = (const float*)d_in[2];
    const float* bd1  = (const float*)d_in[3];
    const float* wd2  = (const float*)d_in[4];
    const float* bd2  = (const float*)d_in[5];
    const float* wg1  = (const float*)d_in[6];
    const float* bg1  = (const float*)d_in[7];
    const float* wg2  = (const float*)d_in[8];
    const float* bg2  = (const float*)d_in[9];
    float* out = (float*)d_out;

    knn_kernel<<<BB * NN / 8, 256>>>(xyz);

    int smem = (ROWS * SA * 2 + 2 * KC * DD + ROWS * 3) * 4 + ROWS * 4;  // ~202 KB
    cudaFuncSetAttribute(mlp_kernel, cudaFuncAttributeMaxDynamicSharedMemorySize, smem);
    mlp_kernel<<<BB * NN / PTS, NT, smem>>>(xyz, feat, wd1, bd1, wd2, bd2,
                                            wg1, bg1, wg2, bg2, out);
}

// round 6
// speedup vs baseline: 4.3987x; 2.1777x over previous
#include <cuda_runtime.h>
#include <cuda_fp16.h>
#include <stdint.h>
#include <math.h>

#define BB 4
#define NN 2048
#define DD 256
#define KK 16
#define PTS 4
#define MROWS 64
#define NT 512

// smem byte offsets
#define OFF_HHI 0
#define OFF_HLO 32768
#define OFF_XHI 65536
#define OFF_XLO 98304
#define OFF_BHI 131072
#define OFF_BLO 163840
#define OFF_SDEL 196608
#define OFF_SIDX 197376
#define OFF_SWD1 197632
#define OFF_SBD1 200704
#define OFF_SBD2 201728
#define OFF_SBG1 202752
#define OFF_SBG2 203776
#define SMEM_TOTAL 204800

__device__ int g_knn[BB * NN * KK];
// [gemm 0..2][hi chunks 0..3, lo chunks 4..7][16384 half] pre-swizzled B images
__device__ __half g_wsplit[3 * 8 * 16384];

// ---------------------------------------------------------------------------
__device__ __forceinline__ uint32_t smem_u32(const void* p) {
    uint32_t a;
    asm("{ .reg .u64 t; cvta.to.shared.u64 t, %1; cvt.u32.u64 %0, t; }" : "=r"(a) : "l"(p));
    return a;
}
__device__ __forceinline__ void cp_async16(void* s, const void* g) {
    uint32_t a = smem_u32(s);
    asm volatile("cp.async.cg.shared.global [%0], [%1], 16;\n" :: "r"(a), "l"(g));
}
__device__ __forceinline__ void cp_commit() { asm volatile("cp.async.commit_group;\n"); }
__device__ __forceinline__ void cp_wait0()  { asm volatile("cp.async.wait_group 0;\n" ::: "memory"); }

__device__ __forceinline__ void ldsm4(uint32_t* r, uint32_t addr) {
    asm volatile("ldmatrix.sync.aligned.m8n8.x4.shared.b16 {%0,%1,%2,%3}, [%4];"
        : "=r"(r[0]), "=r"(r[1]), "=r"(r[2]), "=r"(r[3]) : "r"(addr));
}
__device__ __forceinline__ void mma16816(float* d, const uint32_t* a, uint32_t b0, uint32_t b1) {
    asm volatile("mma.sync.aligned.m16n8k16.row.col.f32.f16.f16.f32 "
        "{%0,%1,%2,%3}, {%4,%5,%6,%7}, {%8,%9}, {%0,%1,%2,%3};"
        : "+f"(d[0]), "+f"(d[1]), "+f"(d[2]), "+f"(d[3])
        : "r"(a[0]), "r"(a[1]), "r"(a[2]), "r"(a[3]), "r"(b0), "r"(b1));
}
__device__ __forceinline__ uint32_t pack2f(float v0, float v1) {
    __half2 h = __floats2half2_rn(v0, v1);
    return *(uint32_t*)&h;
}
__device__ __forceinline__ uint32_t pack2h(__half h0, __half h1) {
    __half2 h = __halves2half2(h0, h1);
    return *(uint32_t*)&h;
}
// A-plane address: [64 rows][256 k] fp16, 512B rows, XOR swizzle in bits 4..6
__device__ __forceinline__ uint32_t aAddr(int row, int col) {
    return (uint32_t)row * 512 + (uint32_t)(((col * 2) ^ ((row & 7) << 4)));
}

// ---------------------------------------------------------------------------
// prep: split fp32 weights into fp16 hi/lo, transpose to [n][k], pre-swizzle
// ---------------------------------------------------------------------------
__global__ void prep_kernel(const float* __restrict__ wd2, const float* __restrict__ wg1,
                            const float* __restrict__ wg2) {
    int t = blockIdx.x * 256 + threadIdx.x;
    if (t >= 3 * 65536) return;
    int g = t >> 16, k = (t >> 8) & 255, n = t & 255;
    const float* W = (g == 0) ? wd2 : ((g == 1) ? wg1 : wg2);
    float v = W[k * 256 + n];
    __half h = __float2half_rn(v);
    __half l = __float2half_rn(v - __half2float(h));
    int chunk = k >> 6, kb = k & 63;
    int byteoff = n * 128 + ((kb * 2) ^ ((n & 7) << 4));
    size_t base = (size_t)g * 8 * 16384;
    g_wsplit[base + (size_t)chunk * 16384 + (byteoff >> 1)] = h;
    g_wsplit[base + (size_t)(4 + chunk) * 16384 + (byteoff >> 1)] = l;
}

// ---------------------------------------------------------------------------
// KNN (validated in prior rounds)
// ---------------------------------------------------------------------------
__global__ __launch_bounds__(256) void knn_kernel(const float* __restrict__ xyz) {
    __shared__ float sx[NN], sy[NN], sz[NN], ssq[NN];
    int b  = blockIdx.x >> 8;
    int q0 = (blockIdx.x & 255) * 8;
    const float* base = xyz + (size_t)b * NN * 3;
    for (int i = threadIdx.x; i < NN; i += 256) {
        float x = base[i*3+0], y = base[i*3+1], z = base[i*3+2];
        sx[i] = x; sy[i] = y; sz[i] = z; ssq[i] = x*x + y*y + z*z;
    }
    __syncthreads();
    int lane = threadIdx.x & 31;
    int q = q0 + (threadIdx.x >> 5);
    float qx = sx[q], qy = sy[q], qz = sz[q], qsq = ssq[q];
    float bd[KK]; int bi[KK];
#pragma unroll
    for (int i = 0; i < KK; i++) { bd[i] = INFINITY; bi[i] = 0; }
    for (int m = lane; m < NN; m += 32) {
        float d = qsq - 2.0f*(qx*sx[m] + qy*sy[m] + qz*sz[m]) + ssq[m];
        if (d < bd[KK-1]) {
            float v = d; int vi = m;
#pragma unroll
            for (int j = 0; j < KK; j++)
                if (v < bd[j]) { float td = bd[j]; int ti = bi[j]; bd[j]=v; bi[j]=vi; v=td; vi=ti; }
        }
    }
    int sel = 0;
    for (int r = 0; r < KK; r++) {
        float m0 = bd[0]; int ml = lane;
#pragma unroll
        for (int off = 16; off; off >>= 1) {
            float om = __shfl_xor_sync(0xffffffffu, m0, off);
            int   ol = __shfl_xor_sync(0xffffffffu, ml, off);
            if (om < m0 || (om == m0 && ol < ml)) { m0 = om; ml = ol; }
        }
        int widx = __shfl_sync(0xffffffffu, bi[0], ml);
        if (lane == r) sel = widx;
        if (lane == ml) {
#pragma unroll
            for (int j = 0; j < KK-1; j++) { bd[j]=bd[j+1]; bi[j]=bi[j+1]; }
            bd[KK-1] = INFINITY;
        }
    }
    if (lane < KK) g_knn[((size_t)b*NN + q)*KK + lane] = sel;
}

// ---------------------------------------------------------------------------
// One emulated-fp32 GEMM: acc(64x256) += A(64x256) @ W^T, 3 fp16 passes.
// ---------------------------------------------------------------------------
__device__ __forceinline__ void run_gemm(const __half* __restrict__ wsplit_g,
                                         char* smemc, uint32_t sb,
                                         uint32_t aHiOff, uint32_t aLoOff,
                                         float acc[8][4], int tid, int wm, int wn)
{
    int lane = tid & 31;
    int ar = lane & 15, ah = lane >> 4;
    uint32_t aRow = sb + (uint32_t)(16*wm + ar) * 512;
    uint32_t aXor = (uint32_t)(ar & 7) << 4;
    int bi = lane & 7, bseg = lane >> 3;
    int bn_add = bi + ((bseg >= 2) ? 8 : 0);
    int bk_add = (bseg & 1) ? 8 : 0;
    uint32_t bXor = (uint32_t)bi << 4;

#pragma unroll
    for (int t = 0; t < 8; t++)
#pragma unroll
        for (int j = 0; j < 4; j++) acc[t][j] = 0.f;

#pragma unroll 1
    for (int c = 0; c < 4; c++) {
        const float4* sh = (const float4*)(wsplit_g + (size_t)c * 16384);
        const float4* sl = (const float4*)(wsplit_g + (size_t)(4 + c) * 16384);
#pragma unroll
        for (int i = 0; i < 4; i++) {
            cp_async16(smemc + OFF_BHI + (tid + i*NT)*16, sh + tid + i*NT);
            cp_async16(smemc + OFF_BLO + (tid + i*NT)*16, sl + tid + i*NT);
        }
        cp_commit(); cp_wait0();
        __syncthreads();
#pragma unroll
        for (int s = 0; s < 4; s++) {
            int kglob = c*64 + s*16;
            uint32_t aCol = (uint32_t)((kglob + 8*ah) * 2) ^ aXor;
            uint32_t ahi[4], alo[4];
            ldsm4(ahi, aRow + aHiOff + aCol);
            ldsm4(alo, aRow + aLoOff + aCol);
            uint32_t bOff = (uint32_t)(((s*16 + bk_add) * 2)) ^ bXor;
#pragma unroll
            for (int tp = 0; tp < 4; tp++) {
                int n = 64*wn + 16*tp + bn_add;
                uint32_t baddr = sb + (uint32_t)n*128 + bOff;
                uint32_t bh[4], bl[4];
                ldsm4(bh, baddr + OFF_BHI);
                ldsm4(bl, baddr + OFF_BLO);
                mma16816(acc[2*tp],   ahi, bh[0], bh[1]);
                mma16816(acc[2*tp+1], ahi, bh[2], bh[3]);
                mma16816(acc[2*tp],   ahi, bl[0], bl[1]);
                mma16816(acc[2*tp+1], ahi, bl[2], bl[3]);
                mma16816(acc[2*tp],   alo, bh[0], bh[1]);
                mma16816(acc[2*tp+1], alo, bh[2], bh[3]);
            }
        }
        __syncthreads();
    }
}

// ---------------------------------------------------------------------------
// Fused block: delta-MLP + gather + gating-MLP + softmax + residual. M=64.
// ---------------------------------------------------------------------------
__global__ __launch_bounds__(NT, 1)
void mlp_kernel(const float* __restrict__ xyz, const float* __restrict__ feat,
                const float* __restrict__ wd1, const float* __restrict__ bd1,
                const float* __restrict__ bd2, const float* __restrict__ bg1,
                const float* __restrict__ bg2, float* __restrict__ out)
{
    extern __shared__ char smemc[];
    uint32_t sb = smem_u32(smemc);
    int tid = threadIdx.x;
    int w = tid >> 5, lane = tid & 31;
    int wm = w & 3, wn = w >> 2;
    int b  = blockIdx.x >> 9;             // 512 CTAs per batch
    int p0 = (blockIdx.x & 511) * PTS;

    float* sdel = (float*)(smemc + OFF_SDEL);
    int*   sidx = (int*)(smemc + OFF_SIDX);
    float* swd1 = (float*)(smemc + OFF_SWD1);
    float* sbd1 = (float*)(smemc + OFF_SBD1);
    float* sbd2 = (float*)(smemc + OFF_SBD2);
    float* sbg1 = (float*)(smemc + OFF_SBG1);
    float* sbg2 = (float*)(smemc + OFF_SBG2);

    if (tid < 256) {
        sbd1[tid] = bd1[tid]; sbd2[tid] = bd2[tid];
        sbg1[tid] = bg1[tid]; sbg2[tid] = bg2[tid];
    }
    for (int i = tid; i < 768; i += NT) swd1[i] = wd1[i];
    if (tid < MROWS) {
        int n = p0 + (tid >> 4);
        int idx = g_knn[((size_t)b*NN + n)*KK + (tid & 15)];
        sidx[tid] = idx;
        const float* xb = xyz + (size_t)b * NN * 3;
        sdel[tid*3+0] = xb[n*3+0] - xb[idx*3+0];
        sdel[tid*3+1] = xb[n*3+1] - xb[idx*3+1];
        sdel[tid*3+2] = xb[n*3+2] - xb[idx*3+2];
    }
    __syncthreads();

    // ---- H1 = relu(delta @ wd1 + bd1) -> H planes (fp16 hi/lo) ----
    {
        int row = tid >> 3;
        int c0 = (tid & 7) * 32;
        float dx = sdel[row*3], dy = sdel[row*3+1], dz = sdel[row*3+2];
#pragma unroll
        for (int jp = 0; jp < 16; jp++) {
            int ch = c0 + jp*2;
            float v0 = fmaxf(fmaf(dz, swd1[512+ch],   fmaf(dy, swd1[256+ch],   fmaf(dx, swd1[ch],   sbd1[ch]))), 0.f);
            float v1 = fmaxf(fmaf(dz, swd1[512+ch+1], fmaf(dy, swd1[256+ch+1], fmaf(dx, swd1[ch+1], sbd1[ch+1]))), 0.f);
            __half h0 = __float2half_rn(v0), h1 = __float2half_rn(v1);
            *(uint32_t*)(smemc + OFF_HHI + aAddr(row, ch)) = pack2h(h0, h1);
            *(uint32_t*)(smemc + OFF_HLO + aAddr(row, ch)) =
                pack2f(v0 - __half2float(h0), v1 - __half2float(h1));
        }
    }
    // (covered by first barrier inside run_gemm)

    float acc[8][4];
    int ra = 16*wm + (lane >> 2), rb = ra + 8;

    // ---- GEMM1: D = H1 @ wd2^T ----
    run_gemm(g_wsplit, smemc, sb, OFF_HHI, OFF_HLO, acc, tid, wm, wn);

    // ---- epi1: x_k = D + bd2 + feat[idx] -> X planes ----
    {
        const float* fb = feat + (size_t)b * NN * DD;
        const float* fra = fb + (size_t)sidx[ra] * DD;
        const float* frb = fb + (size_t)sidx[rb] * DD;
#pragma unroll
        for (int t = 0; t < 8; t++) {
            int ne = 64*wn + 8*t + 2*(lane & 3);
            float2 fa = *(const float2*)(fra + ne);
            float2 fv = *(const float2*)(frb + ne);
            float v0 = acc[t][0] + sbd2[ne]   + fa.x;
            float v1 = acc[t][1] + sbd2[ne+1] + fa.y;
            float v2 = acc[t][2] + sbd2[ne]   + fv.x;
            float v3 = acc[t][3] + sbd2[ne+1] + fv.y;
            __half h0 = __float2half_rn(v0), h1 = __float2half_rn(v1);
            __half h2 = __float2half_rn(v2), h3 = __float2half_rn(v3);
            *(uint32_t*)(smemc + OFF_XHI + aAddr(ra, ne)) = pack2h(h0, h1);
            *(uint32_t*)(smemc + OFF_XLO + aAddr(ra, ne)) =
                pack2f(v0 - __half2float(h0), v1 - __half2float(h1));
            *(uint32_t*)(smemc + OFF_XHI + aAddr(rb, ne)) = pack2h(h2, h3);
            *(uint32_t*)(smemc + OFF_XLO + aAddr(rb, ne)) =
                pack2f(v2 - __half2float(h2), v3 - __half2float(h3));
        }
    }

    // ---- GEMM2: D = x_k @ wg1^T ----
    run_gemm(g_wsplit + 8*16384, smemc, sb, OFF_XHI, OFF_XLO, acc, tid, wm, wn);

    // ---- epi2: H2 = relu(D + bg1) -> H planes ----
    {
#pragma unroll
        for (int t = 0; t < 8; t++) {
            int ne = 64*wn + 8*t + 2*(lane & 3);
            float v0 = fmaxf(acc[t][0] + sbg1[ne],   0.f);
            float v1 = fmaxf(acc[t][1] + sbg1[ne+1], 0.f);
            float v2 = fmaxf(acc[t][2] + sbg1[ne],   0.f);
            float v3 = fmaxf(acc[t][3] + sbg1[ne+1], 0.f);
            __half h0 = __float2half_rn(v0), h1 = __float2half_rn(v1);
            __half h2 = __float2half_rn(v2), h3 = __float2half_rn(v3);
            *(uint32_t*)(smemc + OFF_HHI + aAddr(ra, ne)) = pack2h(h0, h1);
            *(uint32_t*)(smemc + OFF_HLO + aAddr(ra, ne)) =
                pack2f(v0 - __half2float(h0), v1 - __half2float(h1));
            *(uint32_t*)(smemc + OFF_HHI + aAddr(rb, ne)) = pack2h(h2, h3);
            *(uint32_t*)(smemc + OFF_HLO + aAddr(rb, ne)) =
                pack2f(v2 - __half2float(h2), v3 - __half2float(h3));
        }
    }

    // ---- GEMM3: D = H2 @ wg2^T ----
    run_gemm(g_wsplit + 16*16384, smemc, sb, OFF_HHI, OFF_HLO, acc, tid, wm, wn);

    // ---- softmax over k (warp wm owns point wm's 16 rows) + weighted sum ----
    {
        int n_pt = p0 + wm;
        const float* fpt = feat + ((size_t)b*NN + n_pt) * DD;
        float* orow = out + ((size_t)b*NN + n_pt) * DD;
#pragma unroll
        for (int t = 0; t < 8; t++) {
            int ne = 64*wn + 8*t + 2*(lane & 3);
            float g0 = acc[t][0] + sbg2[ne];
            float g1 = acc[t][1] + sbg2[ne+1];
            float g2 = acc[t][2] + sbg2[ne];
            float g3 = acc[t][3] + sbg2[ne+1];
            uint32_t xha = *(uint32_t*)(smemc + OFF_XHI + aAddr(ra, ne));
            uint32_t xla = *(uint32_t*)(smemc + OFF_XLO + aAddr(ra, ne));
            uint32_t xhb = *(uint32_t*)(smemc + OFF_XHI + aAddr(rb, ne));
            uint32_t xlb = *(uint32_t*)(smemc + OFF_XLO + aAddr(rb, ne));
            float2 ha = __half22float2(*(__half2*)&xha), la = __half22float2(*(__half2*)&xla);
            float2 hb = __half22float2(*(__half2*)&xhb), lb = __half22float2(*(__half2*)&xlb);
            float xa0 = ha.x + la.x, xa1 = ha.y + la.y;
            float xb0 = hb.x + lb.x, xb1 = hb.y + lb.y;
            float m0 = fmaxf(g0, g2), m1 = fmaxf(g1, g3);
#pragma unroll
            for (int o = 4; o <= 16; o <<= 1) {
                m0 = fmaxf(m0, __shfl_xor_sync(0xffffffffu, m0, o));
                m1 = fmaxf(m1, __shfl_xor_sync(0xffffffffu, m1, o));
            }
            float e0 = __expf(g0 - m0), e2 = __expf(g2 - m0);
            float e1 = __expf(g1 - m1), e3 = __expf(g3 - m1);
            float se0 = e0 + e2, se1 = e1 + e3;
            float sx0 = e0*xa0 + e2*xb0, sx1 = e1*xa1 + e3*xb1;
#pragma unroll
            for (int o = 4; o <= 16; o <<= 1) {
                se0 += __shfl_xor_sync(0xffffffffu, se0, o);
                se1 += __shfl_xor_sync(0xffffffffu, se1, o);
                sx0 += __shfl_xor_sync(0xffffffffu, sx0, o);
                sx1 += __shfl_xor_sync(0xffffffffu, sx1, o);
            }
            if (lane < 4) {
                float2 f = *(const float2*)(fpt + ne);
                float2 o2 = make_float2(f.x + sx0/se0, f.y + sx1/se1);
                *(float2*)(orow + ne) = o2;
            }
        }
    }
}

// ---------------------------------------------------------------------------
extern "C" void kernel_launch(void* const* d_in, const int* in_sizes, int n_in,
                              void* d_out, int out_size) {
    const float* xyz  = (const float*)d_in[0];
    const float* feat = (const float*)d_in[1];
    const float* wd1  = (const float*)d_in[2];
    const float* bd1  = (const float*)d_in[3];
    const float* wd2  = (const float*)d_in[4];
    const float* bd2  = (const float*)d_in[5];
    const float* wg1  = (const float*)d_in[6];
    const float* bg1  = (const float*)d_in[7];
    const float* wg2  = (const float*)d_in[8];
    const float* bg2  = (const float*)d_in[9];
    float* out = (float*)d_out;

    prep_kernel<<<768, 256>>>(wd2, wg1, wg2);
    knn_kernel<<<BB * NN / 8, 256>>>(xyz);

    cudaFuncSetAttribute(mlp_kernel, cudaFuncAttributeMaxDynamicSharedMemorySize, SMEM_TOTAL);
    mlp_kernel<<<BB * NN / PTS, NT, SMEM_TOTAL>>>(xyz, feat, wd1, bd1,
                                                  bd2, bg1, bg2, out);
}